// round 1
// baseline (speedup 1.0000x reference)
#include <cuda_runtime.h>

// Problem: NLM_7962869366897
//   x1[b,d,h] = GLU_h( (sum_m S[b,d,m] * W1a[m,h,d] + b1a[d,h]) / Ta )   h in [0,128) -> [0,64)
//   out[b,d]  = GLU  ( (sum_h x1[b,d,h] * W1b[h,j,d] + b1b[d,j]) / Tb )  j in {0,1}
// B=512, D=2048, M=32, H=64. All fp32.
//
// Strategy: 1 CTA per d. Stage W1a[:, :, d] into SMEM packed as float4
// (w[h], w[h+64], w[h+32], w[h+96]) so the inner loop is
//   LDS.128 + mov.b64(pack s) + 2x fma.rn.f32x2   per k-step,
// using Blackwell packed f32x2 FMA for 2x fp32 throughput.
// Each warp processes one batch row; lane t owns heads {t, t+32} (and their
// gates {t+64, t+96}); layer 2 is a warp shuffle reduction.

#define DEV_INLINE __device__ __forceinline__

constexpr int kB = 512;
constexpr int kD = 2048;
constexpr int kM = 32;
constexpr int kH = 64;   // 2H = 128

DEV_INLINE unsigned long long pack2(float x) {
    unsigned long long r;
    unsigned int u = __float_as_uint(x);
    asm("mov.b64 %0, {%1, %2};" : "=l"(r) : "r"(u), "r"(u));
    return r;
}

DEV_INLINE void fma2(unsigned long long& acc, unsigned long long a, unsigned long long b) {
    asm("fma.rn.f32x2 %0, %1, %2, %0;" : "+l"(acc) : "l"(a), "l"(b));
}

DEV_INLINE float2 unpack2(unsigned long long v) {
    unsigned int lo, hi;
    asm("mov.b64 {%0, %1}, %2;" : "=r"(lo), "=r"(hi) : "l"(v));
    return make_float2(__uint_as_float(lo), __uint_as_float(hi));
}

DEV_INLINE float fast_sigmoid(float x) {
    return 1.0f / (1.0f + __expf(-x));
}

__global__ __launch_bounds__(256)
void nlm_kernel(const float* __restrict__ state,   // [B, D, M]
                const float* __restrict__ w1a,     // [M, 2H, D]
                const float* __restrict__ b1a,     // [1, D, 2H]
                const float* __restrict__ Ta,      // [1]
                const float* __restrict__ w1b,     // [H, 2, D]
                const float* __restrict__ b1b,     // [1, D, 2]
                const float* __restrict__ Tb,      // [1]
                float* __restrict__ out) {         // [B, D]
    const int d = blockIdx.x;

    __shared__ float4 W1[kM * 32];   // [m][hq]: (w[hq], w[hq+64], w[hq+32], w[hq+96])
    __shared__ float2 W2[kH];        // (w1b[h,0,d], w1b[h,1,d])
    __shared__ float  Bi1[2 * kH];
    __shared__ float  Bi2[2];

    const int tid = threadIdx.x;

    // --- Stage weights/biases for this d into SMEM ---
    for (int i = tid; i < kM * 32; i += 256) {
        const int m = i >> 5;
        const int h = i & 31;
        const float* wp = w1a + ((size_t)m * 128) * kD + d;
        float a0 = __ldg(wp + (size_t)(h)      * kD);
        float a1 = __ldg(wp + (size_t)(h + 64) * kD);
        float a2 = __ldg(wp + (size_t)(h + 32) * kD);
        float a3 = __ldg(wp + (size_t)(h + 96) * kD);
        W1[i] = make_float4(a0, a1, a2, a3);
    }
    if (tid < kH) {
        W2[tid] = make_float2(__ldg(w1b + (size_t)(tid * 2 + 0) * kD + d),
                              __ldg(w1b + (size_t)(tid * 2 + 1) * kD + d));
    }
    if (tid < 2 * kH) Bi1[tid] = b1a[(size_t)d * (2 * kH) + tid];
    if (tid < 2)      Bi2[tid] = b1b[(size_t)d * 2 + tid];
    __syncthreads();

    const float rTa = 1.0f / Ta[0];
    const float rTb = 1.0f / Tb[0];

    const int warp = tid >> 5;
    const int lane = tid & 31;

    // Per-lane constants (lane owns heads lane and lane+32)
    const float b1_0 = Bi1[lane];
    const float b1_1 = Bi1[lane + 64];
    const float b1_2 = Bi1[lane + 32];
    const float b1_3 = Bi1[lane + 96];
    const float2 w2a = W2[lane];
    const float2 w2b = W2[lane + 32];
    const float bi2_0 = Bi2[0];
    const float bi2_1 = Bi2[1];

    const ulonglong2* W1q = reinterpret_cast<const ulonglong2*>(W1);

    for (int b = warp; b < kB; b += 8) {
        // Load s[b,d,:] (32 contiguous floats, warp-uniform -> broadcast LDG)
        const float4* sp = reinterpret_cast<const float4*>(
            state + ((size_t)b * kD + d) * kM);
        float s[kM];
        #pragma unroll
        for (int i = 0; i < 8; i++) {
            float4 v = __ldg(sp + i);
            s[4 * i + 0] = v.x; s[4 * i + 1] = v.y;
            s[4 * i + 2] = v.z; s[4 * i + 3] = v.w;
        }

        unsigned long long acc01 = 0ull;  // f32x2 (0,0)
        unsigned long long acc23 = 0ull;
        #pragma unroll
        for (int m = 0; m < kM; m++) {
            ulonglong2 w = W1q[m * 32 + lane];  // LDS.128: pairs (h,h+64),(h+32,h+96)
            unsigned long long sv = pack2(s[m]);
            fma2(acc01, sv, w.x);
            fma2(acc23, sv, w.y);
        }

        const float2 a01 = unpack2(acc01);
        const float2 a23 = unpack2(acc23);

        // Layer-1 GLU (value * sigmoid(gate)), temperature applied pre-activation
        const float g0 = ((a01.x + b1_0) * rTa) * fast_sigmoid((a01.y + b1_1) * rTa);
        const float g1 = ((a23.x + b1_2) * rTa) * fast_sigmoid((a23.y + b1_3) * rTa);

        // Layer-2 partial products, reduce over 64 heads (2 per lane)
        float p0 = g0 * w2a.x + g1 * w2b.x;
        float p1 = g0 * w2a.y + g1 * w2b.y;
        #pragma unroll
        for (int off = 16; off > 0; off >>= 1) {
            p0 += __shfl_xor_sync(0xffffffffu, p0, off);
            p1 += __shfl_xor_sync(0xffffffffu, p1, off);
        }

        if (lane == 0) {
            const float u0 = (p0 + bi2_0) * rTb;
            const float u1 = (p1 + bi2_1) * rTb;
            out[(size_t)b * kD + d] = u0 * fast_sigmoid(u1);
        }
    }
}

extern "C" void kernel_launch(void* const* d_in, const int* in_sizes, int n_in,
                              void* d_out, int out_size) {
    const float* state = (const float*)d_in[0];
    const float* w1a   = (const float*)d_in[1];
    const float* b1a   = (const float*)d_in[2];
    const float* Ta    = (const float*)d_in[3];
    const float* w1b   = (const float*)d_in[4];
    const float* b1b   = (const float*)d_in[5];
    const float* Tb    = (const float*)d_in[6];
    float* out = (float*)d_out;

    nlm_kernel<<<kD, 256>>>(state, w1a, b1a, Ta, w1b, b1b, Tb, out);
}

// round 2
// speedup vs baseline: 1.7372x; 1.7372x over previous
#include <cuda_runtime.h>

// NLM_7962869366897 — Round 2: 8-row register blocking.
// Each warp owns 64 batch rows, processed in 8 groups of 8. One weight
// LDS.128 per m-step feeds 16 FFMA2 (8 rows x 2 accs), cutting L1 shared
// wavefronts 8x vs round 1 (the measured bottleneck: L1=91.4%).

#define DEV_INLINE __device__ __forceinline__

constexpr int kB = 512;
constexpr int kD = 2048;
constexpr int kM = 32;
constexpr int kH = 64;   // 2H = 128

DEV_INLINE unsigned long long pack2(float x) {
    unsigned long long r;
    unsigned int u = __float_as_uint(x);
    asm("mov.b64 %0, {%1, %2};" : "=l"(r) : "r"(u), "r"(u));
    return r;
}

DEV_INLINE void fma2(unsigned long long& acc, unsigned long long a, unsigned long long b) {
    asm("fma.rn.f32x2 %0, %1, %2, %0;" : "+l"(acc) : "l"(a), "l"(b));
}

DEV_INLINE float2 unpack2(unsigned long long v) {
    unsigned int lo, hi;
    asm("mov.b64 {%0, %1}, %2;" : "=r"(lo), "=r"(hi) : "l"(v));
    return make_float2(__uint_as_float(lo), __uint_as_float(hi));
}

DEV_INLINE float fast_sigmoid(float x) {
    return 1.0f / (1.0f + __expf(-x));
}

__global__ __launch_bounds__(256, 2)
void nlm_kernel(const float* __restrict__ state,   // [B, D, M]
                const float* __restrict__ w1a,     // [M, 2H, D]
                const float* __restrict__ b1a,     // [1, D, 2H]
                const float* __restrict__ Ta,      // [1]
                const float* __restrict__ w1b,     // [H, 2, D]
                const float* __restrict__ b1b,     // [1, D, 2]
                const float* __restrict__ Tb,      // [1]
                float* __restrict__ out) {         // [B, D]
    const int d = blockIdx.x;

    __shared__ float4 W1[kM * 32];   // [m][hq]: (w[hq], w[hq+64], w[hq+32], w[hq+96])
    __shared__ float2 W2[kH];        // (w1b[h,0,d], w1b[h,1,d])
    __shared__ float  Bi1[2 * kH];
    __shared__ float  Bi2[2];

    const int tid = threadIdx.x;

    // --- Stage weights/biases for this d into SMEM (strided: compulsory sectors) ---
    for (int i = tid; i < kM * 32; i += 256) {
        const int m = i >> 5;
        const int h = i & 31;
        const float* wp = w1a + ((size_t)m * 128) * kD + d;
        float a0 = __ldg(wp + (size_t)(h)      * kD);
        float a1 = __ldg(wp + (size_t)(h + 64) * kD);
        float a2 = __ldg(wp + (size_t)(h + 32) * kD);
        float a3 = __ldg(wp + (size_t)(h + 96) * kD);
        W1[i] = make_float4(a0, a1, a2, a3);
    }
    if (tid < kH) {
        W2[tid] = make_float2(__ldg(w1b + (size_t)(tid * 2 + 0) * kD + d),
                              __ldg(w1b + (size_t)(tid * 2 + 1) * kD + d));
    }
    if (tid < 2 * kH) Bi1[tid] = b1a[(size_t)d * (2 * kH) + tid];
    if (tid < 2)      Bi2[tid] = b1b[(size_t)d * 2 + tid];
    __syncthreads();

    const float rTa = 1.0f / Ta[0];
    const float rTb = 1.0f / Tb[0];

    const int warp = tid >> 5;
    const int lane = tid & 31;

    const float b1_0 = Bi1[lane];
    const float b1_1 = Bi1[lane + 64];
    const float b1_2 = Bi1[lane + 32];
    const float b1_3 = Bi1[lane + 96];
    const float2 w2a = W2[lane];
    const float2 w2b = W2[lane + 32];
    const float bi2_0 = Bi2[0];
    const float bi2_1 = Bi2[1];

    const ulonglong2* W1q = reinterpret_cast<const ulonglong2*>(W1);

    // Warp owns rows [warp*64, warp*64+64), in 8 groups of 8.
    const int row_base = warp * 64;
    const size_t row_stride = (size_t)kD * kM;   // floats between consecutive b

    #pragma unroll 1
    for (int g = 0; g < 8; g++) {
        const int b0 = row_base + g * 8;
        const float* sbase = state + ((size_t)b0 * kD + d) * kM;

        unsigned long long acc0[8], acc1[8];
        #pragma unroll
        for (int r = 0; r < 8; r++) { acc0[r] = 0ull; acc1[r] = 0ull; }

        #pragma unroll
        for (int mq = 0; mq < 8; mq++) {
            // Broadcast loads: 4 s-values per row for 8 rows (warp-uniform)
            float4 sv[8];
            #pragma unroll
            for (int r = 0; r < 8; r++) {
                sv[r] = __ldg(reinterpret_cast<const float4*>(sbase + (size_t)r * row_stride) + mq);
            }
            #pragma unroll
            for (int mm = 0; mm < 4; mm++) {
                const ulonglong2 w = W1q[(mq * 4 + mm) * 32 + lane];  // LDS.128, shared by 8 rows
                #pragma unroll
                for (int r = 0; r < 8; r++) {
                    const float* svf = reinterpret_cast<const float*>(&sv[r]);
                    const unsigned long long s2 = pack2(svf[mm]);
                    fma2(acc0[r], s2, w.x);
                    fma2(acc1[r], s2, w.y);
                }
            }
        }

        // Epilogue: GLU1 + layer-2 reduction + GLU2 per row
        #pragma unroll
        for (int r = 0; r < 8; r++) {
            const float2 a01 = unpack2(acc0[r]);
            const float2 a23 = unpack2(acc1[r]);
            const float g0 = ((a01.x + b1_0) * rTa) * fast_sigmoid((a01.y + b1_1) * rTa);
            const float g1 = ((a23.x + b1_2) * rTa) * fast_sigmoid((a23.y + b1_3) * rTa);

            float p0 = g0 * w2a.x + g1 * w2b.x;
            float p1 = g0 * w2a.y + g1 * w2b.y;
            #pragma unroll
            for (int off = 16; off > 0; off >>= 1) {
                p0 += __shfl_xor_sync(0xffffffffu, p0, off);
                p1 += __shfl_xor_sync(0xffffffffu, p1, off);
            }
            if (lane == 0) {
                const float u0 = (p0 + bi2_0) * rTb;
                const float u1 = (p1 + bi2_1) * rTb;
                out[(size_t)(b0 + r) * kD + d] = u0 * fast_sigmoid(u1);
            }
        }
    }
}

extern "C" void kernel_launch(void* const* d_in, const int* in_sizes, int n_in,
                              void* d_out, int out_size) {
    const float* state = (const float*)d_in[0];
    const float* w1a   = (const float*)d_in[1];
    const float* b1a   = (const float*)d_in[2];
    const float* Ta    = (const float*)d_in[3];
    const float* w1b   = (const float*)d_in[4];
    const float* b1b   = (const float*)d_in[5];
    const float* Tb    = (const float*)d_in[6];
    float* out = (float*)d_out;

    nlm_kernel<<<kD, 256>>>(state, w1a, b1a, Ta, w1b, b1b, Tb, out);
}

// round 4
// speedup vs baseline: 3.0572x; 1.7599x over previous
#include <cuda_runtime.h>
#include <cstdint>

// NLM_7962869366897 — Round 4: mma.sync tf32 (compute_103-safe; tcgen05 PTX
// is rejected by this harness's compile target).
// Prepass: w1a[M,2H,D] -> g_wt[D][2H][M], rounded to tf32 (cvt.rna).
// Main: 1 CTA per d, 256 thr. 8 groups of 64 batch rows. SMEM staged in exact
// m16n8k8 fragment layout; mainloop = LDS + HMMA only. GLU in-register
// (value col h and gate col h+64 share the lane/slot), fp32 layer-2 via SMEM.

#define DEV_INLINE __device__ __forceinline__

constexpr int kD  = 2048;
constexpr int kM  = 32;
constexpr int kH2 = 128;
constexpr int kH  = 64;

__device__ float g_wt[(size_t)kD * kH2 * kM];   // [d][h][m], tf32-rounded

DEV_INLINE float tf32_rna(float x) {
    uint32_t u; asm("cvt.rna.tf32.f32 %0, %1;" : "=r"(u) : "f"(x));
    return __uint_as_float(u);
}
DEV_INLINE float fast_sigmoid(float x) {       // single MUFU
    float t; asm("tanh.approx.f32 %0, %1;" : "=f"(t) : "f"(0.5f * x));
    return fmaf(0.5f, t, 0.5f);
}
DEV_INLINE void mma_tf32(float* c, const float4& a, const float2& b) {
    asm volatile(
        "mma.sync.aligned.m16n8k8.row.col.f32.tf32.tf32.f32 "
        "{%0,%1,%2,%3}, {%4,%5,%6,%7}, {%8,%9}, {%0,%1,%2,%3};"
        : "+f"(c[0]), "+f"(c[1]), "+f"(c[2]), "+f"(c[3])
        : "r"(__float_as_uint(a.x)), "r"(__float_as_uint(a.y)),
          "r"(__float_as_uint(a.z)), "r"(__float_as_uint(a.w)),
          "r"(__float_as_uint(b.x)), "r"(__float_as_uint(b.y)));
}

// ---------------- prepass: transpose + tf32 round ----------------
__global__ __launch_bounds__(256)
void transpose_kernel(const float* __restrict__ w1a) {
    __shared__ float tile[32][33];
    const int h  = blockIdx.y;
    const int d0 = blockIdx.x * 32;
    const int lane = threadIdx.x & 31;
    const int w    = threadIdx.x >> 5;
    #pragma unroll
    for (int m = w; m < 32; m += 8)
        tile[m][lane] = w1a[((size_t)(m * kH2 + h)) * kD + d0 + lane];
    __syncthreads();
    #pragma unroll
    for (int dl = w; dl < 32; dl += 8)
        g_wt[((size_t)(d0 + dl) * kH2 + h) * kM + lane] = tf32_rna(tile[lane][dl]);
}

// ---------------- main kernel ----------------
__global__ __launch_bounds__(256, 3)
void nlm_mma_kernel(const float* __restrict__ state,   // [B, D, M]
                    const float* __restrict__ b1a,     // [1, D, 2H]
                    const float* __restrict__ Ta,
                    const float* __restrict__ w1b,     // [H, 2, D]
                    const float* __restrict__ b1b,     // [1, D, 2]
                    const float* __restrict__ Tb,
                    float* __restrict__ out) {         // [B, D]
    __shared__ float4 As[4 * 4 * 32];     // [mt][k][lane] -> a0..a3      (8 KB)
    __shared__ float2 Bs[16 * 4 * 32];    // [ntile][k][lane] -> b0,b1    (16 KB)
    __shared__ float  xs[64 * 65];        // GLU output x[row][h]         (16.6 KB)
    __shared__ float2 sW2[kH];
    __shared__ float  sBi1[kH2];
    __shared__ float  sBi2v[2];

    const int d    = blockIdx.x;
    const int tid  = threadIdx.x;
    const int lane = tid & 31;
    const int wid  = tid >> 5;
    const int mt   = wid & 3;             // m-tile (16 rows) within group
    const int nh   = wid >> 2;            // n-half: cols nh*32..+31 (+64 gates)

    // ---- stage B (once): g_wt[d] into fragment layout ----
    {
        const float* wsrc = g_wt + (size_t)d * kH2 * kM;
        float* Bf = reinterpret_cast<float*>(Bs);
        #pragma unroll
        for (int j = 0; j < 4; j++) {
            const int idx = tid + j * 256;        // 0..1023
            const int h = idx >> 3, c = idx & 7;
            const float4 v = __ldg(reinterpret_cast<const float4*>(wsrc + h * kM) + c);
            const float* vf = reinterpret_cast<const float*>(&v);
            #pragma unroll
            for (int e = 0; e < 4; e++) {
                const int m = c * 4 + e, k = m >> 3, kk = m & 7;
                const int bl = ((h & 7) << 2) | (kk & 3);
                Bf[((((h >> 3) * 4 + k) * 32 + bl) << 1) + (kk >> 2)] = vf[e];
            }
        }
    }
    if (tid < kH)
        sW2[tid] = make_float2(__ldg(w1b + (size_t)(tid * 2 + 0) * kD + d),
                               __ldg(w1b + (size_t)(tid * 2 + 1) * kD + d));
    if (tid < kH2) sBi1[tid] = b1a[(size_t)d * kH2 + tid];
    if (tid < 2)   sBi2v[tid] = b1b[(size_t)d * 2 + tid];
    const float rTa = 1.0f / __ldg(Ta);
    const float rTb = 1.0f / __ldg(Tb);

    const int rrow = tid >> 2;           // layer-2 reduce: row, 4 thr/row
    const int rpart = tid & 3;

    for (int g = 0; g < 8; g++) {
        const int b0 = g * 64;

        // ---- stage A: 64 rows x 32 m -> fragment layout (tf32-rounded) ----
        {
            float* Af = reinterpret_cast<float*>(As);
            #pragma unroll
            for (int j = 0; j < 2; j++) {
                const int idx = tid + j * 256;    // 0..511
                const int row = idx >> 3, c = idx & 7;
                const float4 v = __ldg(reinterpret_cast<const float4*>(
                    state + ((size_t)(b0 + row) * kD + d) * kM) + c);
                const float* vf = reinterpret_cast<const float*>(&v);
                #pragma unroll
                for (int e = 0; e < 4; e++) {
                    const float val = tf32_rna(vf[e]);
                    const int m = c * 4 + e, k = m >> 3, kk = m & 7;
                    const int lr = row & 15;
                    const int al = ((lr & 7) << 2) | (kk & 3);
                    const int r  = (lr >> 3) | ((kk >> 2) << 1);
                    Af[(((((row >> 4) * 4 + k) * 32 + al)) << 2) + r] = val;
                }
            }
        }
        __syncthreads();

        // ---- mainloop: 4 k-steps x 8 n-tiles of HMMA ----
        float acc[8][4];
        #pragma unroll
        for (int q = 0; q < 8; q++)
            #pragma unroll
            for (int r = 0; r < 4; r++) acc[q][r] = 0.0f;

        #pragma unroll
        for (int k = 0; k < 4; k++) {
            const float4 a = As[(mt * 4 + k) * 32 + lane];
            #pragma unroll
            for (int q = 0; q < 8; q++) {
                const int nt = nh * 4 + (q & 3) + ((q >> 2) << 3); // values then gates
                const float2 b = Bs[(nt * 4 + k) * 32 + lane];
                mma_tf32(acc[q], a, b);
            }
        }

        // ---- GLU1 in-register -> xs ----
        #pragma unroll
        for (int q = 0; q < 4; q++) {
            #pragma unroll
            for (int r = 0; r < 4; r++) {
                const int row = mt * 16 + (lane >> 2) + ((r >> 1) << 3);
                const int h   = nh * 32 + q * 8 + ((lane & 3) << 1) + (r & 1);
                const float val = (acc[q][r]     + sBi1[h])      * rTa;
                const float gt  = (acc[q + 4][r] + sBi1[h + 64]) * rTa;
                xs[row * 65 + h] = val * fast_sigmoid(gt);
            }
        }
        __syncthreads();

        // ---- layer 2 + GLU2: 4 threads per row ----
        {
            float p0 = 0.0f, p1 = 0.0f;
            #pragma unroll
            for (int i = 0; i < 16; i++) {
                const int h = rpart * 16 + i;
                const float x = xs[rrow * 65 + h];
                const float2 w2 = sW2[h];
                p0 = fmaf(x, w2.x, p0);
                p1 = fmaf(x, w2.y, p1);
            }
            p0 += __shfl_xor_sync(0xffffffffu, p0, 1);
            p1 += __shfl_xor_sync(0xffffffffu, p1, 1);
            p0 += __shfl_xor_sync(0xffffffffu, p0, 2);
            p1 += __shfl_xor_sync(0xffffffffu, p1, 2);
            if (rpart == 0) {
                const float u0 = (p0 + sBi2v[0]) * rTb;
                const float u1 = (p1 + sBi2v[1]) * rTb;
                out[(size_t)(b0 + rrow) * kD + d] = u0 * fast_sigmoid(u1);
            }
        }
        __syncthreads();   // xs consumed; As safe to restage next group
    }
}

// ---------------- launch ----------------
extern "C" void kernel_launch(void* const* d_in, const int* in_sizes, int n_in,
                              void* d_out, int out_size) {
    const float* state = (const float*)d_in[0];
    const float* w1a   = (const float*)d_in[1];
    const float* b1a   = (const float*)d_in[2];
    const float* Ta    = (const float*)d_in[3];
    const float* w1b   = (const float*)d_in[4];
    const float* b1b   = (const float*)d_in[5];
    const float* Tb    = (const float*)d_in[6];
    float* out = (float*)d_out;

    transpose_kernel<<<dim3(kD / 32, kH2), 256>>>(w1a);
    nlm_mma_kernel<<<kD, 256>>>(state, b1a, Ta, w1b, b1b, Tb, out);
}

// round 5
// speedup vs baseline: 6.5788x; 2.1519x over previous
#include <cuda_runtime.h>
#include <cstdint>

// NLM_7962869366897 — Round 5: ldmatrix staging + m32n64 warp tiles, no xs.
// Prepass: w1a[M,2H,D] -> g_wt[D][2H][M] (tf32-rna).
// Main: 1 CTA/d, 256 thr, 4 groups of 128 batch rows. A,B in natural row-major
// SMEM (144B pitch), fragments via ldmatrix.x4. Warp = m32 x n64 (values h in
// [nh*32,+32) + gates at +64 -> GLU in-register). Layer-2 in-register + quad
// shfl; only ps[128][4] (2KB) crosses SMEM.

#define DEV_INLINE __device__ __forceinline__

constexpr int kD  = 2048;
constexpr int kM  = 32;
constexpr int kH2 = 128;
constexpr int kH  = 64;

__device__ float g_wt[(size_t)kD * kH2 * kM];   // [d][h][m], tf32-rounded

DEV_INLINE float tf32_rna(float x) {
    uint32_t u; asm("cvt.rna.tf32.f32 %0, %1;" : "=r"(u) : "f"(x));
    return __uint_as_float(u);
}
DEV_INLINE float fast_sigmoid(float x) {
    float t; asm("tanh.approx.f32 %0, %1;" : "=f"(t) : "f"(0.5f * x));
    return fmaf(0.5f, t, 0.5f);
}
DEV_INLINE uint32_t smem_u32(const void* p) {
    uint32_t a;
    asm("{ .reg .u64 t; cvta.to.shared.u64 t, %1; cvt.u32.u64 %0, t; }" : "=r"(a) : "l"(p));
    return a;
}
DEV_INLINE void ldsm_x4(uint32_t* r, uint32_t addr) {
    asm volatile("ldmatrix.sync.aligned.m8n8.x4.shared.b16 {%0,%1,%2,%3}, [%4];"
                 : "=r"(r[0]), "=r"(r[1]), "=r"(r[2]), "=r"(r[3]) : "r"(addr));
}
DEV_INLINE void mma_tf32(float* c, const uint32_t* a, const uint32_t* b) {
    asm volatile(
        "mma.sync.aligned.m16n8k8.row.col.f32.tf32.tf32.f32 "
        "{%0,%1,%2,%3}, {%4,%5,%6,%7}, {%8,%9}, {%0,%1,%2,%3};"
        : "+f"(c[0]), "+f"(c[1]), "+f"(c[2]), "+f"(c[3])
        : "r"(a[0]), "r"(a[1]), "r"(a[2]), "r"(a[3]), "r"(b[0]), "r"(b[1]));
}

// ---------------- prepass: transpose + tf32 round ----------------
__global__ __launch_bounds__(256)
void transpose_kernel(const float* __restrict__ w1a) {
    __shared__ float tile[32][33];
    const int h  = blockIdx.y;
    const int d0 = blockIdx.x * 32;
    const int lane = threadIdx.x & 31;
    const int w    = threadIdx.x >> 5;
    #pragma unroll
    for (int m = w; m < 32; m += 8)
        tile[m][lane] = w1a[((size_t)(m * kH2 + h)) * kD + d0 + lane];
    __syncthreads();
    #pragma unroll
    for (int dl = w; dl < 32; dl += 8)
        g_wt[((size_t)(d0 + dl) * kH2 + h) * kM + lane] = tf32_rna(tile[lane][dl]);
}

// ---------------- main kernel ----------------
// SMEM pitch: 36 floats (144 B) per 32-float row -> conflict-free ldmatrix.
constexpr int PITCH = 36;

__global__ __launch_bounds__(256, 2)
void nlm_mma_kernel(const float* __restrict__ state,   // [B, D, M]
                    const float* __restrict__ b1a,     // [1, D, 2H]
                    const float* __restrict__ Ta,
                    const float* __restrict__ w1b,     // [H, 2, D]
                    const float* __restrict__ b1b,     // [1, D, 2]
                    const float* __restrict__ Tb,
                    float* __restrict__ out) {         // [B, D]
    __shared__ float As[128 * PITCH];                  // 18 KB, rows = batch
    __shared__ float Bs[128 * PITCH];                  // 18 KB, rows = h
    __shared__ __align__(16) float ps[128][4];         // layer-2 partials
    __shared__ float2 sW2[kH];
    __shared__ float  sBi1[kH2];
    __shared__ float  sBi2[2];

    const int d    = blockIdx.x;
    const int tid  = threadIdx.x;
    const int lane = tid & 31;
    const int wid  = tid >> 5;
    const int mt   = wid & 3;      // m-tile: rows mt*32..+31 of the 128-row group
    const int nh   = wid >> 2;     // n-half: value cols nh*32..+31, gates +64

    // ---- stage B once (natural [h][m] layout, coalesced) ----
    {
        const float* wsrc = g_wt + (size_t)d * kH2 * kM;
        #pragma unroll
        for (int t = 0; t < 4; t++) {
            const int idx = tid + t * 256;          // 1024 float4s
            const int h = idx >> 3, c = idx & 7;
            *reinterpret_cast<float4*>(Bs + h * PITCH + c * 4) =
                __ldg(reinterpret_cast<const float4*>(wsrc + h * kM) + c);
        }
    }
    if (tid < kH)
        sW2[tid] = make_float2(__ldg(w1b + (size_t)(tid * 2 + 0) * kD + d),
                               __ldg(w1b + (size_t)(tid * 2 + 1) * kD + d));
    if (tid < kH2) sBi1[tid] = b1a[(size_t)d * kH2 + tid];
    if (tid < 2)   sBi2[tid] = b1b[(size_t)d * 2 + tid];
    const float rTa = 1.0f / __ldg(Ta);
    const float rTb = 1.0f / __ldg(Tb);

    // ---- ldmatrix base addresses (bytes) ----
    const uint32_t sA = smem_u32(As), sB = smem_u32(Bs);
    const int g2 = lane >> 3, li = lane & 7;
    // A x4: matrices (rows+0,k0-3),(rows+8,k0-3),(rows+0,k4-7),(rows+8,k4-7)
    const uint32_t aAddr = sA + (uint32_t)(mt * 32 + (g2 & 1) * 8 + li) * 144
                              + (uint32_t)(g2 >> 1) * 16;
    // B x4: matrices (nt,k0-3),(nt,k4-7),(nt+1,k0-3),(nt+1,k4-7)
    const uint32_t bAddrV = sB + (uint32_t)(nh * 32 + (g2 >> 1) * 8 + li) * 144
                               + (uint32_t)(g2 & 1) * 16;
    const uint32_t bAddrG = bAddrV + 64u * 144u;    // gate rows at h+64

    // per-thread epilogue constants
    const int hq = (lane & 3) * 2;                  // col pair within n-tile

    for (int g = 0; g < 4; g++) {
        const int b0 = g * 128;

        // ---- stage A(g) (coalesced LDG.128 -> STS.128, tf32-rna) ----
        #pragma unroll
        for (int t = 0; t < 4; t++) {
            const int idx = tid + t * 256;
            const int row = idx >> 3, c = idx & 7;
            float4 v = __ldg(reinterpret_cast<const float4*>(
                state + ((size_t)(b0 + row) * kD + d) * kM) + c);
            v.x = tf32_rna(v.x); v.y = tf32_rna(v.y);
            v.z = tf32_rna(v.z); v.w = tf32_rna(v.w);
            *reinterpret_cast<float4*>(As + row * PITCH + c * 4) = v;
        }
        // ---- finalize previous group's output (reads ps only) ----
        if (g > 0 && tid < 128) {
            const float4 pp = *reinterpret_cast<const float4*>(&ps[tid][0]);
            const float u0 = (pp.x + pp.z + sBi2[0]) * rTb;
            const float u1 = (pp.y + pp.w + sBi2[1]) * rTb;
            out[(size_t)((g - 1) * 128 + tid) * kD + d] = u0 * fast_sigmoid(u1);
        }
        __syncthreads();

        // ---- init accumulators with layer-1 biases ----
        float acc[2][8][4];
        #pragma unroll
        for (int q = 0; q < 4; q++) {
            const float2 bb = *reinterpret_cast<const float2*>(&sBi1[nh * 32 + q * 8 + hq]);
            const float2 bg = *reinterpret_cast<const float2*>(&sBi1[64 + nh * 32 + q * 8 + hq]);
            #pragma unroll
            for (int f = 0; f < 2; f++) {
                acc[f][q][0] = bb.x; acc[f][q][1] = bb.y;
                acc[f][q][2] = bb.x; acc[f][q][3] = bb.y;
                acc[f][q + 4][0] = bg.x; acc[f][q + 4][1] = bg.y;
                acc[f][q + 4][2] = bg.x; acc[f][q + 4][3] = bg.y;
            }
        }

        // ---- mainloop: 4 k-steps, ldmatrix + 16 HMMA each ----
        #pragma unroll
        for (int k = 0; k < 4; k++) {
            uint32_t a0[4], a1[4], bv0[4], bv1[4], bg0[4], bg1[4];
            ldsm_x4(a0, aAddr + k * 32);
            ldsm_x4(a1, aAddr + 16 * 144 + k * 32);       // rows +16 (2nd m-frag)
            ldsm_x4(bv0, bAddrV + k * 32);                // value n-tiles 0,1
            ldsm_x4(bv1, bAddrV + 16 * 144 + k * 32);     // value n-tiles 2,3
            ldsm_x4(bg0, bAddrG + k * 32);                // gate  n-tiles 0,1
            ldsm_x4(bg1, bAddrG + 16 * 144 + k * 32);     // gate  n-tiles 2,3

            mma_tf32(acc[0][0], a0, bv0 + 0); mma_tf32(acc[0][1], a0, bv0 + 2);
            mma_tf32(acc[0][2], a0, bv1 + 0); mma_tf32(acc[0][3], a0, bv1 + 2);
            mma_tf32(acc[0][4], a0, bg0 + 0); mma_tf32(acc[0][5], a0, bg0 + 2);
            mma_tf32(acc[0][6], a0, bg1 + 0); mma_tf32(acc[0][7], a0, bg1 + 2);
            mma_tf32(acc[1][0], a1, bv0 + 0); mma_tf32(acc[1][1], a1, bv0 + 2);
            mma_tf32(acc[1][2], a1, bv1 + 0); mma_tf32(acc[1][3], a1, bv1 + 2);
            mma_tf32(acc[1][4], a1, bg0 + 0); mma_tf32(acc[1][5], a1, bg0 + 2);
            mma_tf32(acc[1][6], a1, bg1 + 0); mma_tf32(acc[1][7], a1, bg1 + 2);
        }

        // ---- GLU1 + layer-2 partials in-register, quad reduce -> ps ----
        float4 w2q[4];
        #pragma unroll
        for (int q = 0; q < 4; q++)
            w2q[q] = *reinterpret_cast<const float4*>(&sW2[nh * 32 + q * 8 + hq]);

        #pragma unroll
        for (int f = 0; f < 2; f++) {
            #pragma unroll
            for (int rh = 0; rh < 2; rh++) {
                float p0 = 0.0f, p1 = 0.0f;
                #pragma unroll
                for (int q = 0; q < 4; q++) {
                    const float x0 = (acc[f][q][rh * 2 + 0] * rTa) *
                                     fast_sigmoid(acc[f][q + 4][rh * 2 + 0] * rTa);
                    const float x1 = (acc[f][q][rh * 2 + 1] * rTa) *
                                     fast_sigmoid(acc[f][q + 4][rh * 2 + 1] * rTa);
                    p0 = fmaf(x0, w2q[q].x, p0); p1 = fmaf(x0, w2q[q].y, p1);
                    p0 = fmaf(x1, w2q[q].z, p0); p1 = fmaf(x1, w2q[q].w, p1);
                }
                p0 += __shfl_xor_sync(0xffffffffu, p0, 1);
                p0 += __shfl_xor_sync(0xffffffffu, p0, 2);
                p1 += __shfl_xor_sync(0xffffffffu, p1, 1);
                p1 += __shfl_xor_sync(0xffffffffu, p1, 2);
                if ((lane & 3) == 0) {
                    const int row = mt * 32 + f * 16 + rh * 8 + (lane >> 2);
                    *reinterpret_cast<float2*>(&ps[row][nh * 2]) = make_float2(p0, p1);
                }
            }
        }
        __syncthreads();
    }

    // ---- finalize last group ----
    if (tid < 128) {
        const float4 pp = *reinterpret_cast<const float4*>(&ps[tid][0]);
        const float u0 = (pp.x + pp.z + sBi2[0]) * rTb;
        const float u1 = (pp.y + pp.w + sBi2[1]) * rTb;
        out[(size_t)(3 * 128 + tid) * kD + d] = u0 * fast_sigmoid(u1);
    }
}

// ---------------- launch ----------------
extern "C" void kernel_launch(void* const* d_in, const int* in_sizes, int n_in,
                              void* d_out, int out_size) {
    const float* state = (const float*)d_in[0];
    const float* w1a   = (const float*)d_in[1];
    const float* b1a   = (const float*)d_in[2];
    const float* Ta    = (const float*)d_in[3];
    const float* w1b   = (const float*)d_in[4];
    const float* b1b   = (const float*)d_in[5];
    const float* Tb    = (const float*)d_in[6];
    float* out = (float*)d_out;

    transpose_kernel<<<dim3(kD / 32, kH2), 256>>>(w1a);
    nlm_mma_kernel<<<kD, 256>>>(state, b1a, Ta, w1b, b1b, Tb, out);
}

// round 6
// speedup vs baseline: 7.4620x; 1.1342x over previous
#include <cuda_runtime.h>
#include <cstdint>

// NLM_7962869366897 — Round 6: cp.async double-buffered A staging.
// Same math as Round 5 (mma.sync tf32, m32n64 warp tiles, GLU in-register),
// but A(g+1) streams into the alternate SMEM buffer via cp.async.cg while
// group g computes, removing the serialized LDG->STS->sync latency that held
// the kernel at occ=24%/issue=37%. A is rna-rounded post-ldsm (ALU) since
// cp.async is a raw copy; weights stay pre-rounded by the prepass.

#define DEV_INLINE __device__ __forceinline__

constexpr int kD  = 2048;
constexpr int kM  = 32;
constexpr int kH2 = 128;
constexpr int kH  = 64;

__device__ float g_wt[(size_t)kD * kH2 * kM];   // [d][h][m], tf32-rounded

DEV_INLINE float tf32_rna(float x) {
    uint32_t u; asm("cvt.rna.tf32.f32 %0, %1;" : "=r"(u) : "f"(x));
    return __uint_as_float(u);
}
DEV_INLINE uint32_t rna_u(uint32_t x) {
    uint32_t u; asm("cvt.rna.tf32.f32 %0, %1;" : "=r"(u) : "f"(__uint_as_float(x)));
    return u;
}
DEV_INLINE float fast_sigmoid(float x) {
    float t; asm("tanh.approx.f32 %0, %1;" : "=f"(t) : "f"(0.5f * x));
    return fmaf(0.5f, t, 0.5f);
}
DEV_INLINE uint32_t smem_u32(const void* p) {
    uint32_t a;
    asm("{ .reg .u64 t; cvta.to.shared.u64 t, %1; cvt.u32.u64 %0, t; }" : "=r"(a) : "l"(p));
    return a;
}
DEV_INLINE void ldsm_x4(uint32_t* r, uint32_t addr) {
    asm volatile("ldmatrix.sync.aligned.m8n8.x4.shared.b16 {%0,%1,%2,%3}, [%4];"
                 : "=r"(r[0]), "=r"(r[1]), "=r"(r[2]), "=r"(r[3]) : "r"(addr));
}
DEV_INLINE void mma_tf32(float* c, const uint32_t* a, const uint32_t* b) {
    asm volatile(
        "mma.sync.aligned.m16n8k8.row.col.f32.tf32.tf32.f32 "
        "{%0,%1,%2,%3}, {%4,%5,%6,%7}, {%8,%9}, {%0,%1,%2,%3};"
        : "+f"(c[0]), "+f"(c[1]), "+f"(c[2]), "+f"(c[3])
        : "r"(a[0]), "r"(a[1]), "r"(a[2]), "r"(a[3]), "r"(b[0]), "r"(b[1]));
}
DEV_INLINE void cp_async16(uint32_t dst, const void* src) {
    asm volatile("cp.async.cg.shared.global [%0], [%1], 16;"
                 :: "r"(dst), "l"(__cvta_generic_to_global(src)) : "memory");
}
#define CP_COMMIT() asm volatile("cp.async.commit_group;" ::: "memory")
#define CP_WAIT0()  asm volatile("cp.async.wait_group 0;" ::: "memory")

// ---------------- prepass: transpose + tf32 round ----------------
__global__ __launch_bounds__(256)
void transpose_kernel(const float* __restrict__ w1a) {
    __shared__ float tile[32][33];
    const int h  = blockIdx.y;
    const int d0 = blockIdx.x * 32;
    const int lane = threadIdx.x & 31;
    const int w    = threadIdx.x >> 5;
    #pragma unroll
    for (int m = w; m < 32; m += 8)
        tile[m][lane] = w1a[((size_t)(m * kH2 + h)) * kD + d0 + lane];
    __syncthreads();
    #pragma unroll
    for (int dl = w; dl < 32; dl += 8)
        g_wt[((size_t)(d0 + dl) * kH2 + h) * kM + lane] = tf32_rna(tile[lane][dl]);
}

// ---------------- main kernel ----------------
constexpr int PITCH   = 36;                 // floats per 32-float row (144 B)
constexpr int AFLOATS = 128 * PITCH;        // one A buffer (4608 floats)
constexpr int ABYTES  = AFLOATS * 4;        // 18432 B
// dynamic smem layout (floats): As[2] | Bs | ps | W2 | Bi1 | Bi2
constexpr int OFF_B   = 2 * AFLOATS;        // 9216
constexpr int OFF_PS  = OFF_B + AFLOATS;    // 13824  (ps = 128*4)
constexpr int OFF_W2  = OFF_PS + 512;       // 14336  (float2[64] = 128 floats)
constexpr int OFF_BI1 = OFF_W2 + 128;       // 14464
constexpr int OFF_BI2 = OFF_BI1 + 128;      // 14592
constexpr int SMEM_FLOATS = OFF_BI2 + 4;    // 14596
constexpr int SMEM_BYTES  = SMEM_FLOATS * 4;

__global__ __launch_bounds__(256, 2)
void nlm_mma_kernel(const float* __restrict__ state,   // [B, D, M]
                    const float* __restrict__ b1a,     // [1, D, 2H]
                    const float* __restrict__ Ta,
                    const float* __restrict__ w1b,     // [H, 2, D]
                    const float* __restrict__ b1b,     // [1, D, 2]
                    const float* __restrict__ Tb,
                    float* __restrict__ out) {         // [B, D]
    extern __shared__ float sm[];
    float*  As   = sm;
    float*  Bs   = sm + OFF_B;
    float*  ps   = sm + OFF_PS;
    float2* sW2  = reinterpret_cast<float2*>(sm + OFF_W2);
    float*  sBi1 = sm + OFF_BI1;
    float*  sBi2 = sm + OFF_BI2;

    const int d    = blockIdx.x;
    const int tid  = threadIdx.x;
    const int lane = tid & 31;
    const int wid  = tid >> 5;
    const int mt   = wid & 3;      // m-tile: rows mt*32..+31
    const int nh   = wid >> 2;     // n-half: value cols nh*32..+31, gates +64

    const uint32_t sA0 = smem_u32(As);
    const uint32_t sB0 = smem_u32(Bs);

    // ---- stage B + A(0) via cp.async ----
    {
        const float* wsrc = g_wt + (size_t)d * kH2 * kM;
        #pragma unroll
        for (int t = 0; t < 4; t++) {
            const int idx = tid + t * 256;
            const int r = idx >> 3, c = idx & 7;
            cp_async16(sB0 + (uint32_t)(r * PITCH + c * 4) * 4, wsrc + r * kM + c * 4);
            cp_async16(sA0 + (uint32_t)(r * PITCH + c * 4) * 4,
                       state + ((size_t)r * kD + d) * kM + c * 4);
        }
        CP_COMMIT();
    }
    if (tid < kH)
        sW2[tid] = make_float2(__ldg(w1b + (size_t)(tid * 2 + 0) * kD + d),
                               __ldg(w1b + (size_t)(tid * 2 + 1) * kD + d));
    if (tid < kH2) sBi1[tid] = b1a[(size_t)d * kH2 + tid];
    if (tid < 2)   sBi2[tid] = b1b[(size_t)d * 2 + tid];
    const float rTa = 1.0f / __ldg(Ta);
    const float rTb = 1.0f / __ldg(Tb);

    // ---- ldmatrix base addresses ----
    const int g2 = lane >> 3, li = lane & 7;
    const uint32_t aAddr = sA0 + (uint32_t)(mt * 32 + (g2 & 1) * 8 + li) * 144
                               + (uint32_t)(g2 >> 1) * 16;
    const uint32_t bAddrV = sB0 + (uint32_t)(nh * 32 + (g2 >> 1) * 8 + li) * 144
                                + (uint32_t)(g2 & 1) * 16;
    const uint32_t bAddrG = bAddrV + 64u * 144u;
    const int hq = (lane & 3) * 2;

    CP_WAIT0();
    __syncthreads();

    for (int g = 0; g < 4; g++) {
        // ---- prefetch A(g+1) into the other buffer (overlaps with MMA) ----
        if (g < 3) {
            const uint32_t dstb = sA0 + (uint32_t)(((g + 1) & 1) * ABYTES);
            const int b0n = (g + 1) * 128;
            #pragma unroll
            for (int t = 0; t < 4; t++) {
                const int idx = tid + t * 256;
                const int r = idx >> 3, c = idx & 7;
                cp_async16(dstb + (uint32_t)(r * PITCH + c * 4) * 4,
                           state + ((size_t)(b0n + r) * kD + d) * kM + c * 4);
            }
            CP_COMMIT();
        }
        // ---- finalize previous group's output ----
        if (g > 0 && tid < 128) {
            const float4 pp = *reinterpret_cast<const float4*>(&ps[tid * 4]);
            const float u0 = (pp.x + pp.z + sBi2[0]) * rTb;
            const float u1 = (pp.y + pp.w + sBi2[1]) * rTb;
            out[(size_t)((g - 1) * 128 + tid) * kD + d] = u0 * fast_sigmoid(u1);
        }

        // ---- init accumulators with layer-1 biases ----
        float acc[2][8][4];
        #pragma unroll
        for (int q = 0; q < 4; q++) {
            const float2 bb = *reinterpret_cast<const float2*>(&sBi1[nh * 32 + q * 8 + hq]);
            const float2 bg = *reinterpret_cast<const float2*>(&sBi1[64 + nh * 32 + q * 8 + hq]);
            #pragma unroll
            for (int f = 0; f < 2; f++) {
                acc[f][q][0] = bb.x; acc[f][q][1] = bb.y;
                acc[f][q][2] = bb.x; acc[f][q][3] = bb.y;
                acc[f][q + 4][0] = bg.x; acc[f][q + 4][1] = bg.y;
                acc[f][q + 4][2] = bg.x; acc[f][q + 4][3] = bg.y;
            }
        }

        // ---- mainloop on buffer g&1 ----
        const uint32_t aA = aAddr + (uint32_t)((g & 1) * ABYTES);
        #pragma unroll
        for (int k = 0; k < 4; k++) {
            uint32_t a0[4], a1[4], bv0[4], bv1[4], bg0[4], bg1[4];
            ldsm_x4(a0, aA + k * 32);
            ldsm_x4(a1, aA + 16 * 144 + k * 32);
            ldsm_x4(bv0, bAddrV + k * 32);
            ldsm_x4(bv1, bAddrV + 16 * 144 + k * 32);
            ldsm_x4(bg0, bAddrG + k * 32);
            ldsm_x4(bg1, bAddrG + 16 * 144 + k * 32);
            #pragma unroll
            for (int j = 0; j < 4; j++) { a0[j] = rna_u(a0[j]); a1[j] = rna_u(a1[j]); }

            mma_tf32(acc[0][0], a0, bv0 + 0); mma_tf32(acc[0][1], a0, bv0 + 2);
            mma_tf32(acc[0][2], a0, bv1 + 0); mma_tf32(acc[0][3], a0, bv1 + 2);
            mma_tf32(acc[0][4], a0, bg0 + 0); mma_tf32(acc[0][5], a0, bg0 + 2);
            mma_tf32(acc[0][6], a0, bg1 + 0); mma_tf32(acc[0][7], a0, bg1 + 2);
            mma_tf32(acc[1][0], a1, bv0 + 0); mma_tf32(acc[1][1], a1, bv0 + 2);
            mma_tf32(acc[1][2], a1, bv1 + 0); mma_tf32(acc[1][3], a1, bv1 + 2);
            mma_tf32(acc[1][4], a1, bg0 + 0); mma_tf32(acc[1][5], a1, bg0 + 2);
            mma_tf32(acc[1][6], a1, bg1 + 0); mma_tf32(acc[1][7], a1, bg1 + 2);
        }

        // ---- GLU1 + layer-2 partials, quad reduce -> ps ----
        float4 w2q[4];
        #pragma unroll
        for (int q = 0; q < 4; q++)
            w2q[q] = *reinterpret_cast<const float4*>(&sW2[nh * 32 + q * 8 + hq]);

        #pragma unroll
        for (int f = 0; f < 2; f++) {
            #pragma unroll
            for (int rh = 0; rh < 2; rh++) {
                float p0 = 0.0f, p1 = 0.0f;
                #pragma unroll
                for (int q = 0; q < 4; q++) {
                    const float x0 = (acc[f][q][rh * 2 + 0] * rTa) *
                                     fast_sigmoid(acc[f][q + 4][rh * 2 + 0] * rTa);
                    const float x1 = (acc[f][q][rh * 2 + 1] * rTa) *
                                     fast_sigmoid(acc[f][q + 4][rh * 2 + 1] * rTa);
                    p0 = fmaf(x0, w2q[q].x, p0); p1 = fmaf(x0, w2q[q].y, p1);
                    p0 = fmaf(x1, w2q[q].z, p0); p1 = fmaf(x1, w2q[q].w, p1);
                }
                p0 += __shfl_xor_sync(0xffffffffu, p0, 1);
                p0 += __shfl_xor_sync(0xffffffffu, p0, 2);
                p1 += __shfl_xor_sync(0xffffffffu, p1, 1);
                p1 += __shfl_xor_sync(0xffffffffu, p1, 2);
                if ((lane & 3) == 0) {
                    const int row = mt * 32 + f * 16 + rh * 8 + (lane >> 2);
                    *reinterpret_cast<float2*>(&ps[row * 4 + nh * 2]) = make_float2(p0, p1);
                }
            }
        }

        if (g < 3) CP_WAIT0();    // A(g+1) landed
        __syncthreads();          // ps ready + next buffer ready
    }

    // ---- finalize last group ----
    if (tid < 128) {
        const float4 pp = *reinterpret_cast<const float4*>(&ps[tid * 4]);
        const float u0 = (pp.x + pp.z + sBi2[0]) * rTb;
        const float u1 = (pp.y + pp.w + sBi2[1]) * rTb;
        out[(size_t)(3 * 128 + tid) * kD + d] = u0 * fast_sigmoid(u1);
    }
}

// ---------------- launch ----------------
extern "C" void kernel_launch(void* const* d_in, const int* in_sizes, int n_in,
                              void* d_out, int out_size) {
    const float* state = (const float*)d_in[0];
    const float* w1a   = (const float*)d_in[1];
    const float* b1a   = (const float*)d_in[2];
    const float* Ta    = (const float*)d_in[3];
    const float* w1b   = (const float*)d_in[4];
    const float* b1b   = (const float*)d_in[5];
    const float* Tb    = (const float*)d_in[6];
    float* out = (float*)d_out;

    cudaFuncSetAttribute(nlm_mma_kernel,
                         cudaFuncAttributeMaxDynamicSharedMemorySize, SMEM_BYTES);

    transpose_kernel<<<dim3(kD / 32, kH2), 256>>>(w1a);
    nlm_mma_kernel<<<kD, 256, SMEM_BYTES>>>(state, b1a, Ta, w1b, b1b, Tb, out);
}

// round 7
// speedup vs baseline: 7.7774x; 1.0423x over previous
#include <cuda_runtime.h>
#include <cstdint>

// NLM_7962869366897 — Round 7: truncation-compensated tf32 + k-pipelined ldsm.
// vs R6: (1) A is fed to the tf32 MMA as raw fp32 bits (HW truncates low 13
// bits); the mean truncation shrink (2^-11*ln2 = 3.385e-4) is compensated by
// scaling the weights in the prepass, so no cvt.rna in the mainloop at all.
// (2) Fragment double-buffering across k-steps: next k's 6 ldsm issue while
// current k's 16 MMAs run, hiding LDS latency (the measured issue-bound stall).

#define DEV_INLINE __device__ __forceinline__

constexpr int kD  = 2048;
constexpr int kM  = 32;
constexpr int kH2 = 128;
constexpr int kH  = 64;

// Mean relative shrink of fp32->tf32 truncation: 2^-11 * ln(2).
constexpr float kTruncComp = 1.00033845f;

__device__ float g_wt[(size_t)kD * kH2 * kM];   // [d][h][m], tf32(rna), pre-scaled

DEV_INLINE float tf32_rna(float x) {
    uint32_t u; asm("cvt.rna.tf32.f32 %0, %1;" : "=r"(u) : "f"(x));
    return __uint_as_float(u);
}
DEV_INLINE float fast_sigmoid(float x) {
    float t; asm("tanh.approx.f32 %0, %1;" : "=f"(t) : "f"(0.5f * x));
    return fmaf(0.5f, t, 0.5f);
}
DEV_INLINE uint32_t smem_u32(const void* p) {
    uint32_t a;
    asm("{ .reg .u64 t; cvta.to.shared.u64 t, %1; cvt.u32.u64 %0, t; }" : "=r"(a) : "l"(p));
    return a;
}
DEV_INLINE void ldsm_x4(uint32_t* r, uint32_t addr) {
    asm volatile("ldmatrix.sync.aligned.m8n8.x4.shared.b16 {%0,%1,%2,%3}, [%4];"
                 : "=r"(r[0]), "=r"(r[1]), "=r"(r[2]), "=r"(r[3]) : "r"(addr));
}
DEV_INLINE void mma_tf32(float* c, const uint32_t* a, const uint32_t* b) {
    asm volatile(
        "mma.sync.aligned.m16n8k8.row.col.f32.tf32.tf32.f32 "
        "{%0,%1,%2,%3}, {%4,%5,%6,%7}, {%8,%9}, {%0,%1,%2,%3};"
        : "+f"(c[0]), "+f"(c[1]), "+f"(c[2]), "+f"(c[3])
        : "r"(a[0]), "r"(a[1]), "r"(a[2]), "r"(a[3]), "r"(b[0]), "r"(b[1]));
}
DEV_INLINE void cp_async16(uint32_t dst, const void* src) {
    asm volatile("cp.async.cg.shared.global [%0], [%1], 16;"
                 :: "r"(dst), "l"(__cvta_generic_to_global(src)) : "memory");
}
#define CP_COMMIT() asm volatile("cp.async.commit_group;" ::: "memory")
#define CP_WAIT0()  asm volatile("cp.async.wait_group 0;" ::: "memory")

// ---------------- prepass: transpose + compensate + tf32 round ----------------
__global__ __launch_bounds__(256)
void transpose_kernel(const float* __restrict__ w1a) {
    __shared__ float tile[32][33];
    const int h  = blockIdx.y;
    const int d0 = blockIdx.x * 32;
    const int lane = threadIdx.x & 31;
    const int w    = threadIdx.x >> 5;
    #pragma unroll
    for (int m = w; m < 32; m += 8)
        tile[m][lane] = w1a[((size_t)(m * kH2 + h)) * kD + d0 + lane];
    __syncthreads();
    #pragma unroll
    for (int dl = w; dl < 32; dl += 8)
        g_wt[((size_t)(d0 + dl) * kH2 + h) * kM + lane] =
            tf32_rna(tile[lane][dl] * kTruncComp);
}

// ---------------- main kernel ----------------
constexpr int PITCH   = 36;                 // floats per 32-float row (144 B)
constexpr int AFLOATS = 128 * PITCH;
constexpr int ABYTES  = AFLOATS * 4;        // 18432 B
constexpr int OFF_B   = 2 * AFLOATS;
constexpr int OFF_PS  = OFF_B + AFLOATS;
constexpr int OFF_W2  = OFF_PS + 512;
constexpr int OFF_BI1 = OFF_W2 + 128;
constexpr int OFF_BI2 = OFF_BI1 + 128;
constexpr int SMEM_FLOATS = OFF_BI2 + 4;
constexpr int SMEM_BYTES  = SMEM_FLOATS * 4;

__global__ __launch_bounds__(256, 2)
void nlm_mma_kernel(const float* __restrict__ state,   // [B, D, M]
                    const float* __restrict__ b1a,     // [1, D, 2H]
                    const float* __restrict__ Ta,
                    const float* __restrict__ w1b,     // [H, 2, D]
                    const float* __restrict__ b1b,     // [1, D, 2]
                    const float* __restrict__ Tb,
                    float* __restrict__ out) {         // [B, D]
    extern __shared__ float sm[];
    float*  As   = sm;
    float*  Bs   = sm + OFF_B;
    float*  ps   = sm + OFF_PS;
    float2* sW2  = reinterpret_cast<float2*>(sm + OFF_W2);
    float*  sBi1 = sm + OFF_BI1;
    float*  sBi2 = sm + OFF_BI2;

    const int d    = blockIdx.x;
    const int tid  = threadIdx.x;
    const int lane = tid & 31;
    const int wid  = tid >> 5;
    const int mt   = wid & 3;      // m-tile: rows mt*32..+31
    const int nh   = wid >> 2;     // n-half: value cols nh*32..+31, gates +64

    const uint32_t sA0 = smem_u32(As);
    const uint32_t sB0 = smem_u32(Bs);

    // ---- stage B + A(0) via cp.async ----
    {
        const float* wsrc = g_wt + (size_t)d * kH2 * kM;
        #pragma unroll
        for (int t = 0; t < 4; t++) {
            const int idx = tid + t * 256;
            const int r = idx >> 3, c = idx & 7;
            cp_async16(sB0 + (uint32_t)(r * PITCH + c * 4) * 4, wsrc + r * kM + c * 4);
            cp_async16(sA0 + (uint32_t)(r * PITCH + c * 4) * 4,
                       state + ((size_t)r * kD + d) * kM + c * 4);
        }
        CP_COMMIT();
    }
    if (tid < kH)
        sW2[tid] = make_float2(__ldg(w1b + (size_t)(tid * 2 + 0) * kD + d),
                               __ldg(w1b + (size_t)(tid * 2 + 1) * kD + d));
    if (tid < kH2) sBi1[tid] = b1a[(size_t)d * kH2 + tid];
    if (tid < 2)   sBi2[tid] = b1b[(size_t)d * 2 + tid];
    const float rTa = 1.0f / __ldg(Ta);
    const float rTb = 1.0f / __ldg(Tb);

    // ---- ldmatrix base addresses ----
    const int g2 = lane >> 3, li = lane & 7;
    const uint32_t aAddr = sA0 + (uint32_t)(mt * 32 + (g2 & 1) * 8 + li) * 144
                               + (uint32_t)(g2 >> 1) * 16;
    const uint32_t bAddrV = sB0 + (uint32_t)(nh * 32 + (g2 >> 1) * 8 + li) * 144
                                + (uint32_t)(g2 & 1) * 16;
    const uint32_t bAddrG = bAddrV + 64u * 144u;
    const int hq = (lane & 3) * 2;

    CP_WAIT0();
    __syncthreads();

    for (int g = 0; g < 4; g++) {
        // ---- prefetch A(g+1) (overlaps with MMA) ----
        if (g < 3) {
            const uint32_t dstb = sA0 + (uint32_t)(((g + 1) & 1) * ABYTES);
            const int b0n = (g + 1) * 128;
            #pragma unroll
            for (int t = 0; t < 4; t++) {
                const int idx = tid + t * 256;
                const int r = idx >> 3, c = idx & 7;
                cp_async16(dstb + (uint32_t)(r * PITCH + c * 4) * 4,
                           state + ((size_t)(b0n + r) * kD + d) * kM + c * 4);
            }
            CP_COMMIT();
        }
        // ---- finalize previous group's output ----
        if (g > 0 && tid < 128) {
            const float4 pp = *reinterpret_cast<const float4*>(&ps[tid * 4]);
            const float u0 = (pp.x + pp.z + sBi2[0]) * rTb;
            const float u1 = (pp.y + pp.w + sBi2[1]) * rTb;
            out[(size_t)((g - 1) * 128 + tid) * kD + d] = u0 * fast_sigmoid(u1);
        }

        // ---- init accumulators with layer-1 biases ----
        float acc[2][8][4];
        #pragma unroll
        for (int q = 0; q < 4; q++) {
            const float2 bb = *reinterpret_cast<const float2*>(&sBi1[nh * 32 + q * 8 + hq]);
            const float2 bg = *reinterpret_cast<const float2*>(&sBi1[64 + nh * 32 + q * 8 + hq]);
            #pragma unroll
            for (int f = 0; f < 2; f++) {
                acc[f][q][0] = bb.x; acc[f][q][1] = bb.y;
                acc[f][q][2] = bb.x; acc[f][q][3] = bb.y;
                acc[f][q + 4][0] = bg.x; acc[f][q + 4][1] = bg.y;
                acc[f][q + 4][2] = bg.x; acc[f][q + 4][3] = bg.y;
            }
        }

        // ---- mainloop on buffer g&1, fragments double-buffered across k ----
        const uint32_t aA = aAddr + (uint32_t)((g & 1) * ABYTES);
        uint32_t fa[2][8], fbv[2][8], fbg[2][8];

        ldsm_x4(fa[0] + 0,  aA);
        ldsm_x4(fa[0] + 4,  aA + 16 * 144);
        ldsm_x4(fbv[0] + 0, bAddrV);
        ldsm_x4(fbv[0] + 4, bAddrV + 16 * 144);
        ldsm_x4(fbg[0] + 0, bAddrG);
        ldsm_x4(fbg[0] + 4, bAddrG + 16 * 144);

        #pragma unroll
        for (int k = 0; k < 4; k++) {
            const int cur = k & 1, nxt = cur ^ 1;
            if (k < 3) {   // prefetch k+1 fragments; overlaps the 16 MMAs below
                ldsm_x4(fa[nxt] + 0,  aA + (k + 1) * 32);
                ldsm_x4(fa[nxt] + 4,  aA + 16 * 144 + (k + 1) * 32);
                ldsm_x4(fbv[nxt] + 0, bAddrV + (k + 1) * 32);
                ldsm_x4(fbv[nxt] + 4, bAddrV + 16 * 144 + (k + 1) * 32);
                ldsm_x4(fbg[nxt] + 0, bAddrG + (k + 1) * 32);
                ldsm_x4(fbg[nxt] + 4, bAddrG + 16 * 144 + (k + 1) * 32);
            }
            const uint32_t* a0 = fa[cur] + 0;
            const uint32_t* a1 = fa[cur] + 4;
            const uint32_t* bv = fbv[cur];
            const uint32_t* bg = fbg[cur];

            mma_tf32(acc[0][0], a0, bv + 0); mma_tf32(acc[0][1], a0, bv + 2);
            mma_tf32(acc[0][2], a0, bv + 4); mma_tf32(acc[0][3], a0, bv + 6);
            mma_tf32(acc[0][4], a0, bg + 0); mma_tf32(acc[0][5], a0, bg + 2);
            mma_tf32(acc[0][6], a0, bg + 4); mma_tf32(acc[0][7], a0, bg + 6);
            mma_tf32(acc[1][0], a1, bv + 0); mma_tf32(acc[1][1], a1, bv + 2);
            mma_tf32(acc[1][2], a1, bv + 4); mma_tf32(acc[1][3], a1, bv + 6);
            mma_tf32(acc[1][4], a1, bg + 0); mma_tf32(acc[1][5], a1, bg + 2);
            mma_tf32(acc[1][6], a1, bg + 4); mma_tf32(acc[1][7], a1, bg + 6);
        }

        // ---- GLU1 + layer-2 partials, quad reduce -> ps ----
        float4 w2q[4];
        #pragma unroll
        for (int q = 0; q < 4; q++)
            w2q[q] = *reinterpret_cast<const float4*>(&sW2[nh * 32 + q * 8 + hq]);

        #pragma unroll
        for (int f = 0; f < 2; f++) {
            #pragma unroll
            for (int rh = 0; rh < 2; rh++) {
                float p0 = 0.0f, p1 = 0.0f;
                #pragma unroll
                for (int q = 0; q < 4; q++) {
                    const float x0 = (acc[f][q][rh * 2 + 0] * rTa) *
                                     fast_sigmoid(acc[f][q + 4][rh * 2 + 0] * rTa);
                    const float x1 = (acc[f][q][rh * 2 + 1] * rTa) *
                                     fast_sigmoid(acc[f][q + 4][rh * 2 + 1] * rTa);
                    p0 = fmaf(x0, w2q[q].x, p0); p1 = fmaf(x0, w2q[q].y, p1);
                    p0 = fmaf(x1, w2q[q].z, p0); p1 = fmaf(x1, w2q[q].w, p1);
                }
                p0 += __shfl_xor_sync(0xffffffffu, p0, 1);
                p0 += __shfl_xor_sync(0xffffffffu, p0, 2);
                p1 += __shfl_xor_sync(0xffffffffu, p1, 1);
                p1 += __shfl_xor_sync(0xffffffffu, p1, 2);
                if ((lane & 3) == 0) {
                    const int row = mt * 32 + f * 16 + rh * 8 + (lane >> 2);
                    *reinterpret_cast<float2*>(&ps[row * 4 + nh * 2]) = make_float2(p0, p1);
                }
            }
        }

        if (g < 3) CP_WAIT0();
        __syncthreads();
    }

    // ---- finalize last group ----
    if (tid < 128) {
        const float4 pp = *reinterpret_cast<const float4*>(&ps[tid * 4]);
        const float u0 = (pp.x + pp.z + sBi2[0]) * rTb;
        const float u1 = (pp.y + pp.w + sBi2[1]) * rTb;
        out[(size_t)(3 * 128 + tid) * kD + d] = u0 * fast_sigmoid(u1);
    }
}

// ---------------- launch ----------------
extern "C" void kernel_launch(void* const* d_in, const int* in_sizes, int n_in,
                              void* d_out, int out_size) {
    const float* state = (const float*)d_in[0];
    const float* w1a   = (const float*)d_in[1];
    const float* b1a   = (const float*)d_in[2];
    const float* Ta    = (const float*)d_in[3];
    const float* w1b   = (const float*)d_in[4];
    const float* b1b   = (const float*)d_in[5];
    const float* Tb    = (const float*)d_in[6];
    float* out = (float*)d_out;

    cudaFuncSetAttribute(nlm_mma_kernel,
                         cudaFuncAttributeMaxDynamicSharedMemorySize, SMEM_BYTES);

    transpose_kernel<<<dim3(kD / 32, kH2), 256>>>(w1a);
    nlm_mma_kernel<<<kD, 256, SMEM_BYTES>>>(state, b1a, Ta, w1b, b1b, Tb, out);
}

// round 8
// speedup vs baseline: 8.4646x; 1.0884x over previous
#include <cuda_runtime.h>
#include <cuda_fp16.h>
#include <cstdint>

// NLM_7962869366897 — Round 8: fp16 m16n8k16 MMA (fp32 accumulate).
// fp16 RN has the same 10-bit mantissa as tf32-rna -> same accuracy class,
// but half the SMEM bytes (L1 was the measured 55% bottleneck), half the MMA
// instructions (k16), and full-rate tensor throughput. Weights converted to
// fp16 in the prepass; A converted in-kernel via LDG.128 prefetch -> cvt ->
// STS (double-buffered). B staged once per CTA via cp.async.

#define DEV_INLINE __device__ __forceinline__

constexpr int kD  = 2048;
constexpr int kM  = 32;
constexpr int kH2 = 128;
constexpr int kH  = 64;

__device__ __half g_wt[(size_t)kD * kH2 * kM];   // [d][h][m], fp16

DEV_INLINE float fast_sigmoid(float x) {
    float t; asm("tanh.approx.f32 %0, %1;" : "=f"(t) : "f"(0.5f * x));
    return fmaf(0.5f, t, 0.5f);
}
DEV_INLINE uint32_t smem_u32(const void* p) {
    uint32_t a;
    asm("{ .reg .u64 t; cvta.to.shared.u64 t, %1; cvt.u32.u64 %0, t; }" : "=r"(a) : "l"(p));
    return a;
}
DEV_INLINE void ldsm_x4(uint32_t* r, uint32_t addr) {
    asm volatile("ldmatrix.sync.aligned.m8n8.x4.shared.b16 {%0,%1,%2,%3}, [%4];"
                 : "=r"(r[0]), "=r"(r[1]), "=r"(r[2]), "=r"(r[3]) : "r"(addr));
}
DEV_INLINE void mma_f16(float* c, const uint32_t* a, const uint32_t* b) {
    asm volatile(
        "mma.sync.aligned.m16n8k16.row.col.f32.f16.f16.f32 "
        "{%0,%1,%2,%3}, {%4,%5,%6,%7}, {%8,%9}, {%0,%1,%2,%3};"
        : "+f"(c[0]), "+f"(c[1]), "+f"(c[2]), "+f"(c[3])
        : "r"(a[0]), "r"(a[1]), "r"(a[2]), "r"(a[3]), "r"(b[0]), "r"(b[1]));
}
DEV_INLINE void cp_async16(uint32_t dst, const void* src) {
    asm volatile("cp.async.cg.shared.global [%0], [%1], 16;"
                 :: "r"(dst), "l"(__cvta_generic_to_global(src)) : "memory");
}
#define CP_COMMIT() asm volatile("cp.async.commit_group;" ::: "memory")
#define CP_WAIT0()  asm volatile("cp.async.wait_group 0;" ::: "memory")

// ---------------- prepass: transpose + fp16 convert ----------------
__global__ __launch_bounds__(256)
void transpose_kernel(const float* __restrict__ w1a) {
    __shared__ float tile[32][33];
    const int h  = blockIdx.y;
    const int d0 = blockIdx.x * 32;
    const int lane = threadIdx.x & 31;
    const int w    = threadIdx.x >> 5;
    #pragma unroll
    for (int m = w; m < 32; m += 8)
        tile[m][lane] = w1a[((size_t)(m * kH2 + h)) * kD + d0 + lane];
    __syncthreads();
    #pragma unroll
    for (int dl = w; dl < 32; dl += 8)
        g_wt[((size_t)(d0 + dl) * kH2 + h) * kM + lane] =
            __float2half_rn(tile[lane][dl]);
}

// ---------------- main kernel ----------------
// fp16 rows: 32 halves = 64 B data, 80 B pitch (bank stride 20 -> ldsm
// conflict-free). Buffers: Ah[2] | Bh | ps | W2 | Bi1 | Bi2.
constexpr int PITCH_B   = 80;                 // bytes per row
constexpr int ABYTES_H  = 128 * PITCH_B;      // 10240
constexpr int OFF_BH    = 2 * ABYTES_H;       // 20480
constexpr int OFF_PS    = OFF_BH + ABYTES_H;  // 30720 (ps: 128*4 floats)
constexpr int OFF_W2    = OFF_PS + 2048;      // 32768 (float2[64])
constexpr int OFF_BI1   = OFF_W2 + 512;       // 33280
constexpr int OFF_BI2   = OFF_BI1 + 512;      // 33792
constexpr int SMEM_BYTES = OFF_BI2 + 32;      // 33824

__global__ __launch_bounds__(256, 2)
void nlm_mma_kernel(const float* __restrict__ state,   // [B, D, M]
                    const float* __restrict__ b1a,     // [1, D, 2H]
                    const float* __restrict__ Ta,
                    const float* __restrict__ w1b,     // [H, 2, D]
                    const float* __restrict__ b1b,     // [1, D, 2]
                    const float* __restrict__ Tb,
                    float* __restrict__ out) {         // [B, D]
    extern __shared__ __align__(16) char sm[];
    char*   Ah   = sm;
    char*   Bh   = sm + OFF_BH;
    float*  ps   = reinterpret_cast<float*>(sm + OFF_PS);
    float2* sW2  = reinterpret_cast<float2*>(sm + OFF_W2);
    float*  sBi1 = reinterpret_cast<float*>(sm + OFF_BI1);
    float*  sBi2 = reinterpret_cast<float*>(sm + OFF_BI2);

    const int d    = blockIdx.x;
    const int tid  = threadIdx.x;
    const int lane = tid & 31;
    const int wid  = tid >> 5;
    const int mt   = wid & 3;      // m-tile: rows mt*32..+31
    const int nh   = wid >> 2;     // n-half: value cols nh*32..+31, gates +64

    const uint32_t sAh = smem_u32(Ah);
    const uint32_t sBh = smem_u32(Bh);

    // per-thread A staging role: row = tid>>1, col half = tid&1 (16 floats)
    const int arow  = tid >> 1;
    const int ahalf = tid & 1;

    // ---- stage B via cp.async (raw fp16 copy) ----
    {
        const char* wsrc = reinterpret_cast<const char*>(g_wt + (size_t)d * kH2 * kM);
        #pragma unroll
        for (int t = 0; t < 2; t++) {
            const int c = tid + t * 256;            // 512 16B chunks
            const int h = c >> 2, cc = c & 3;
            cp_async16(sBh + (uint32_t)(h * PITCH_B + cc * 16), wsrc + h * 64 + cc * 16);
        }
        CP_COMMIT();
    }
    // ---- stage A(0): LDG -> cvt -> STS ----
    {
        const float4* src = reinterpret_cast<const float4*>(
            state + ((size_t)arow * kD + d) * kM + ahalf * 16);
        float4 pf[4];
        #pragma unroll
        for (int j = 0; j < 4; j++) pf[j] = __ldg(src + j);
        __half2 hh[8];
        #pragma unroll
        for (int j = 0; j < 4; j++) {
            hh[2 * j + 0] = __floats2half2_rn(pf[j].x, pf[j].y);
            hh[2 * j + 1] = __floats2half2_rn(pf[j].z, pf[j].w);
        }
        char* dst = Ah + arow * PITCH_B + ahalf * 32;
        *reinterpret_cast<uint4*>(dst)      = *reinterpret_cast<uint4*>(&hh[0]);
        *reinterpret_cast<uint4*>(dst + 16) = *reinterpret_cast<uint4*>(&hh[4]);
    }
    if (tid < kH)
        sW2[tid] = make_float2(__ldg(w1b + (size_t)(tid * 2 + 0) * kD + d),
                               __ldg(w1b + (size_t)(tid * 2 + 1) * kD + d));
    if (tid < kH2) sBi1[tid] = b1a[(size_t)d * kH2 + tid];
    if (tid < 2)   sBi2[tid] = b1b[(size_t)d * 2 + tid];
    const float rTa = 1.0f / __ldg(Ta);
    const float rTb = 1.0f / __ldg(Tb);

    // ---- ldmatrix addresses (non-trans, k-contiguous rows) ----
    // A: mats (m0-7,k0-7),(m8-15,k0-7),(m0-7,k8-15),(m8-15,k8-15)
    const uint32_t aBase = sAh +
        (uint32_t)((mt * 32 + ((lane >> 3) & 1) * 8 + (lane & 7)) * PITCH_B +
                   (lane >> 4) * 16);
    // B: mats (n0-7,k0-7),(n0-7,k8-15),(n8-15,k0-7),(n8-15,k8-15)
    const uint32_t bBase = sBh +
        (uint32_t)((nh * 32 + ((lane >> 4) & 1) * 8 + (lane & 7)) * PITCH_B +
                   ((lane >> 3) & 1) * 16);
    const int hq = (lane & 3) * 2;

    CP_WAIT0();
    __syncthreads();

    for (int g = 0; g < 4; g++) {
        // ---- prefetch A(g+1) into registers (covered by MMA+epilogue) ----
        float4 pf[4];
        if (g < 3) {
            const float4* src = reinterpret_cast<const float4*>(
                state + ((size_t)((g + 1) * 128 + arow) * kD + d) * kM + ahalf * 16);
            #pragma unroll
            for (int j = 0; j < 4; j++) pf[j] = __ldg(src + j);
        }
        // ---- finalize previous group's output ----
        if (g > 0 && tid < 128) {
            const float4 pp = *reinterpret_cast<const float4*>(&ps[tid * 4]);
            const float u0 = (pp.x + pp.z + sBi2[0]) * rTb;
            const float u1 = (pp.y + pp.w + sBi2[1]) * rTb;
            out[(size_t)((g - 1) * 128 + tid) * kD + d] = u0 * fast_sigmoid(u1);
        }

        // ---- init accumulators with layer-1 biases ----
        float acc[2][8][4];
        #pragma unroll
        for (int q = 0; q < 4; q++) {
            const float2 bb = *reinterpret_cast<const float2*>(&sBi1[nh * 32 + q * 8 + hq]);
            const float2 bg = *reinterpret_cast<const float2*>(&sBi1[64 + nh * 32 + q * 8 + hq]);
            #pragma unroll
            for (int f = 0; f < 2; f++) {
                acc[f][q][0] = bb.x; acc[f][q][1] = bb.y;
                acc[f][q][2] = bb.x; acc[f][q][3] = bb.y;
                acc[f][q + 4][0] = bg.x; acc[f][q + 4][1] = bg.y;
                acc[f][q + 4][2] = bg.x; acc[f][q + 4][3] = bg.y;
            }
        }

        // ---- mainloop: 2 k16-steps, 16 MMA each ----
        const uint32_t aA = aBase + (uint32_t)((g & 1) * ABYTES_H);
        #pragma unroll
        for (int k = 0; k < 2; k++) {
            uint32_t a0[4], a1[4], bv[8], bg[8];
            ldsm_x4(a0, aA + k * 32);                       // m-frag rows +0..15
            ldsm_x4(a1, aA + 16 * PITCH_B + k * 32);        // rows +16..31
            ldsm_x4(bv + 0, bBase + k * 32);                // value n-tiles 0,1
            ldsm_x4(bv + 4, bBase + 16 * PITCH_B + k * 32); // value n-tiles 2,3
            ldsm_x4(bg + 0, bBase + 64 * PITCH_B + k * 32); // gate  n-tiles 0,1
            ldsm_x4(bg + 4, bBase + 80 * PITCH_B + k * 32); // gate  n-tiles 2,3

            mma_f16(acc[0][0], a0, bv + 0); mma_f16(acc[0][1], a0, bv + 2);
            mma_f16(acc[0][2], a0, bv + 4); mma_f16(acc[0][3], a0, bv + 6);
            mma_f16(acc[0][4], a0, bg + 0); mma_f16(acc[0][5], a0, bg + 2);
            mma_f16(acc[0][6], a0, bg + 4); mma_f16(acc[0][7], a0, bg + 6);
            mma_f16(acc[1][0], a1, bv + 0); mma_f16(acc[1][1], a1, bv + 2);
            mma_f16(acc[1][2], a1, bv + 4); mma_f16(acc[1][3], a1, bv + 6);
            mma_f16(acc[1][4], a1, bg + 0); mma_f16(acc[1][5], a1, bg + 2);
            mma_f16(acc[1][6], a1, bg + 4); mma_f16(acc[1][7], a1, bg + 6);
        }

        // ---- GLU1 + layer-2 partials, quad reduce -> ps ----
        float4 w2q[4];
        #pragma unroll
        for (int q = 0; q < 4; q++)
            w2q[q] = *reinterpret_cast<const float4*>(&sW2[nh * 32 + q * 8 + hq]);

        #pragma unroll
        for (int f = 0; f < 2; f++) {
            #pragma unroll
            for (int rh = 0; rh < 2; rh++) {
                float p0 = 0.0f, p1 = 0.0f;
                #pragma unroll
                for (int q = 0; q < 4; q++) {
                    const float x0 = (acc[f][q][rh * 2 + 0] * rTa) *
                                     fast_sigmoid(acc[f][q + 4][rh * 2 + 0] * rTa);
                    const float x1 = (acc[f][q][rh * 2 + 1] * rTa) *
                                     fast_sigmoid(acc[f][q + 4][rh * 2 + 1] * rTa);
                    p0 = fmaf(x0, w2q[q].x, p0); p1 = fmaf(x0, w2q[q].y, p1);
                    p0 = fmaf(x1, w2q[q].z, p0); p1 = fmaf(x1, w2q[q].w, p1);
                }
                p0 += __shfl_xor_sync(0xffffffffu, p0, 1);
                p0 += __shfl_xor_sync(0xffffffffu, p0, 2);
                p1 += __shfl_xor_sync(0xffffffffu, p1, 1);
                p1 += __shfl_xor_sync(0xffffffffu, p1, 2);
                if ((lane & 3) == 0) {
                    const int row = mt * 32 + f * 16 + rh * 8 + (lane >> 2);
                    *reinterpret_cast<float2*>(&ps[row * 4 + nh * 2]) = make_float2(p0, p1);
                }
            }
        }

        // ---- convert+store prefetched A(g+1) into the other buffer ----
        if (g < 3) {
            __half2 hh[8];
            #pragma unroll
            for (int j = 0; j < 4; j++) {
                hh[2 * j + 0] = __floats2half2_rn(pf[j].x, pf[j].y);
                hh[2 * j + 1] = __floats2half2_rn(pf[j].z, pf[j].w);
            }
            char* dst = Ah + ((g + 1) & 1) * ABYTES_H + arow * PITCH_B + ahalf * 32;
            *reinterpret_cast<uint4*>(dst)      = *reinterpret_cast<uint4*>(&hh[0]);
            *reinterpret_cast<uint4*>(dst + 16) = *reinterpret_cast<uint4*>(&hh[4]);
        }
        __syncthreads();   // ps visible + next A buffer ready
    }

    // ---- finalize last group ----
    if (tid < 128) {
        const float4 pp = *reinterpret_cast<const float4*>(&ps[tid * 4]);
        const float u0 = (pp.x + pp.z + sBi2[0]) * rTb;
        const float u1 = (pp.y + pp.w + sBi2[1]) * rTb;
        out[(size_t)(3 * 128 + tid) * kD + d] = u0 * fast_sigmoid(u1);
    }
}

// ---------------- launch ----------------
extern "C" void kernel_launch(void* const* d_in, const int* in_sizes, int n_in,
                              void* d_out, int out_size) {
    const float* state = (const float*)d_in[0];
    const float* w1a   = (const float*)d_in[1];
    const float* b1a   = (const float*)d_in[2];
    const float* Ta    = (const float*)d_in[3];
    const float* w1b   = (const float*)d_in[4];
    const float* b1b   = (const float*)d_in[5];
    const float* Tb    = (const float*)d_in[6];
    float* out = (float*)d_out;

    cudaFuncSetAttribute(nlm_mma_kernel,
                         cudaFuncAttributeMaxDynamicSharedMemorySize, SMEM_BYTES);

    transpose_kernel<<<dim3(kD / 32, kH2), 256>>>(w1a);
    nlm_mma_kernel<<<kD, 256, SMEM_BYTES>>>(state, b1a, Ta, w1b, b1b, Tb, out);
}

// round 9
// speedup vs baseline: 8.7166x; 1.0298x over previous
#include <cuda_runtime.h>
#include <cuda_fp16.h>
#include <cstdint>

// NLM_7962869366897 — Round 9: coalesced A staging + cross-group B-register
// residency. R8 post-mortem: A's per-thread-contiguous LDG pattern cost 4
// wavefronts per 128B line (L1 rose to 70%); fixed with row=idx>>3,c=idx&7
// mapping (1 wf/line). B fragments are group-invariant -> loaded once into 32
// registers, removing 3/4 of mainloop ldsm traffic.

#define DEV_INLINE __device__ __forceinline__

constexpr int kD  = 2048;
constexpr int kM  = 32;
constexpr int kH2 = 128;
constexpr int kH  = 64;

__device__ __half g_wt[(size_t)kD * kH2 * kM];   // [d][h][m], fp16

DEV_INLINE float fast_sigmoid(float x) {
    float t; asm("tanh.approx.f32 %0, %1;" : "=f"(t) : "f"(0.5f * x));
    return fmaf(0.5f, t, 0.5f);
}
DEV_INLINE uint32_t smem_u32(const void* p) {
    uint32_t a;
    asm("{ .reg .u64 t; cvta.to.shared.u64 t, %1; cvt.u32.u64 %0, t; }" : "=r"(a) : "l"(p));
    return a;
}
DEV_INLINE void ldsm_x4(uint32_t* r, uint32_t addr) {
    asm volatile("ldmatrix.sync.aligned.m8n8.x4.shared.b16 {%0,%1,%2,%3}, [%4];"
                 : "=r"(r[0]), "=r"(r[1]), "=r"(r[2]), "=r"(r[3]) : "r"(addr));
}
DEV_INLINE void mma_f16(float* c, const uint32_t* a, const uint32_t* b) {
    asm volatile(
        "mma.sync.aligned.m16n8k16.row.col.f32.f16.f16.f32 "
        "{%0,%1,%2,%3}, {%4,%5,%6,%7}, {%8,%9}, {%0,%1,%2,%3};"
        : "+f"(c[0]), "+f"(c[1]), "+f"(c[2]), "+f"(c[3])
        : "r"(a[0]), "r"(a[1]), "r"(a[2]), "r"(a[3]), "r"(b[0]), "r"(b[1]));
}
DEV_INLINE void cp_async16(uint32_t dst, const void* src) {
    asm volatile("cp.async.cg.shared.global [%0], [%1], 16;"
                 :: "r"(dst), "l"(__cvta_generic_to_global(src)) : "memory");
}
#define CP_COMMIT() asm volatile("cp.async.commit_group;" ::: "memory")
#define CP_WAIT0()  asm volatile("cp.async.wait_group 0;" ::: "memory")

DEV_INLINE void sts_half8(char* dst, float4 v) {
    __half2 h0 = __floats2half2_rn(v.x, v.y);
    __half2 h1 = __floats2half2_rn(v.z, v.w);
    uint2 u;
    u.x = *reinterpret_cast<uint32_t*>(&h0);
    u.y = *reinterpret_cast<uint32_t*>(&h1);
    *reinterpret_cast<uint2*>(dst) = u;
}

// ---------------- prepass: transpose + fp16 convert ----------------
__global__ __launch_bounds__(256)
void transpose_kernel(const float* __restrict__ w1a) {
    __shared__ float tile[32][33];
    const int h  = blockIdx.y;
    const int d0 = blockIdx.x * 32;
    const int lane = threadIdx.x & 31;
    const int w    = threadIdx.x >> 5;
    #pragma unroll
    for (int m = w; m < 32; m += 8)
        tile[m][lane] = w1a[((size_t)(m * kH2 + h)) * kD + d0 + lane];
    __syncthreads();
    #pragma unroll
    for (int dl = w; dl < 32; dl += 8)
        g_wt[((size_t)(d0 + dl) * kH2 + h) * kM + lane] =
            __float2half_rn(tile[lane][dl]);
}

// ---------------- main kernel ----------------
constexpr int PITCH_B   = 80;                 // bytes per fp16 row (ldsm-safe)
constexpr int ABYTES_H  = 128 * PITCH_B;      // 10240
constexpr int OFF_BH    = 2 * ABYTES_H;       // 20480
constexpr int OFF_PS    = OFF_BH + ABYTES_H;  // 30720
constexpr int OFF_W2    = OFF_PS + 2048;
constexpr int OFF_BI1   = OFF_W2 + 512;
constexpr int OFF_BI2   = OFF_BI1 + 512;
constexpr int SMEM_BYTES = OFF_BI2 + 32;

__global__ __launch_bounds__(256, 2)
void nlm_mma_kernel(const float* __restrict__ state,   // [B, D, M]
                    const float* __restrict__ b1a,     // [1, D, 2H]
                    const float* __restrict__ Ta,
                    const float* __restrict__ w1b,     // [H, 2, D]
                    const float* __restrict__ b1b,     // [1, D, 2]
                    const float* __restrict__ Tb,
                    float* __restrict__ out) {         // [B, D]
    extern __shared__ __align__(16) char sm[];
    char*   Ah   = sm;
    char*   Bh   = sm + OFF_BH;
    float*  ps   = reinterpret_cast<float*>(sm + OFF_PS);
    float2* sW2  = reinterpret_cast<float2*>(sm + OFF_W2);
    float*  sBi1 = reinterpret_cast<float*>(sm + OFF_BI1);
    float*  sBi2 = reinterpret_cast<float*>(sm + OFF_BI2);

    const int d    = blockIdx.x;
    const int tid  = threadIdx.x;
    const int lane = tid & 31;
    const int wid  = tid >> 5;
    const int mt   = wid & 3;      // m-tile: rows mt*32..+31
    const int nh   = wid >> 2;     // n-half: value cols nh*32..+31, gates +64

    const uint32_t sAh = smem_u32(Ah);
    const uint32_t sBh = smem_u32(Bh);

    // coalesced A staging roles (per 256-float4 pass): row = idx>>3, c = idx&7
    const int arow = tid >> 3;     // base row for t=0 pass
    const int ac   = tid & 7;      // float4 chunk (16B fp32 -> 8B fp16)

    // ---- stage B via cp.async (raw fp16 copy) ----
    {
        const char* wsrc = reinterpret_cast<const char*>(g_wt + (size_t)d * kH2 * kM);
        #pragma unroll
        for (int t = 0; t < 2; t++) {
            const int c = tid + t * 256;
            const int h = c >> 2, cc = c & 3;
            cp_async16(sBh + (uint32_t)(h * PITCH_B + cc * 16), wsrc + h * 64 + cc * 16);
        }
        CP_COMMIT();
    }
    // ---- stage A(0): coalesced LDG.128 -> cvt -> STS.64 ----
    #pragma unroll
    for (int t = 0; t < 4; t++) {
        const int row = arow + t * 32;
        const float4 v = __ldg(reinterpret_cast<const float4*>(
            state + ((size_t)row * kD + d) * kM) + ac);
        sts_half8(Ah + row * PITCH_B + ac * 8, v);
    }
    if (tid < kH)
        sW2[tid] = make_float2(__ldg(w1b + (size_t)(tid * 2 + 0) * kD + d),
                               __ldg(w1b + (size_t)(tid * 2 + 1) * kD + d));
    if (tid < kH2) sBi1[tid] = b1a[(size_t)d * kH2 + tid];
    if (tid < 2)   sBi2[tid] = b1b[(size_t)d * 2 + tid];
    const float rTa = 1.0f / __ldg(Ta);
    const float rTb = 1.0f / __ldg(Tb);

    // ---- ldmatrix addresses ----
    const uint32_t aBase = sAh +
        (uint32_t)((mt * 32 + ((lane >> 3) & 1) * 8 + (lane & 7)) * PITCH_B +
                   (lane >> 4) * 16);
    const uint32_t bBase = sBh +
        (uint32_t)((nh * 32 + ((lane >> 4) & 1) * 8 + (lane & 7)) * PITCH_B +
                   ((lane >> 3) & 1) * 16);
    const int hq = (lane & 3) * 2;

    CP_WAIT0();
    __syncthreads();

    // ---- B fragments: load ONCE, registers for all 4 groups (32 regs) ----
    uint32_t fbv[2][8], fbg[2][8];
    #pragma unroll
    for (int k = 0; k < 2; k++) {
        ldsm_x4(fbv[k] + 0, bBase + k * 32);
        ldsm_x4(fbv[k] + 4, bBase + 16 * PITCH_B + k * 32);
        ldsm_x4(fbg[k] + 0, bBase + 64 * PITCH_B + k * 32);
        ldsm_x4(fbg[k] + 4, bBase + 80 * PITCH_B + k * 32);
    }

    for (int g = 0; g < 4; g++) {
        // ---- prefetch A(g+1) phase 1 (chunks t=0,1) ----
        float4 pf0, pf1;
        const float* nsrc = state + ((size_t)((g + 1) * 128) * kD + d) * kM;
        if (g < 3) {
            pf0 = __ldg(reinterpret_cast<const float4*>(nsrc + (size_t)arow * kD * 0
                        + ((size_t)(arow)) * kD * kM / kM) + 0);  // placeholder avoided below
        }
        // (computed properly below; keep compiler from fusing)
        if (g < 3) {
            pf0 = __ldg(reinterpret_cast<const float4*>(
                nsrc + (size_t)(arow) * kD * kM + 0) + ac);
            pf1 = __ldg(reinterpret_cast<const float4*>(
                nsrc + (size_t)(arow + 32) * kD * kM + 0) + ac);
        }
        // ---- finalize previous group's output ----
        if (g > 0 && tid < 128) {
            const float4 pp = *reinterpret_cast<const float4*>(&ps[tid * 4]);
            const float u0 = (pp.x + pp.z + sBi2[0]) * rTb;
            const float u1 = (pp.y + pp.w + sBi2[1]) * rTb;
            out[(size_t)((g - 1) * 128 + tid) * kD + d] = u0 * fast_sigmoid(u1);
        }

        // ---- init accumulators with layer-1 biases ----
        float acc[2][8][4];
        #pragma unroll
        for (int q = 0; q < 4; q++) {
            const float2 bb = *reinterpret_cast<const float2*>(&sBi1[nh * 32 + q * 8 + hq]);
            const float2 bg = *reinterpret_cast<const float2*>(&sBi1[64 + nh * 32 + q * 8 + hq]);
            #pragma unroll
            for (int f = 0; f < 2; f++) {
                acc[f][q][0] = bb.x; acc[f][q][1] = bb.y;
                acc[f][q][2] = bb.x; acc[f][q][3] = bb.y;
                acc[f][q + 4][0] = bg.x; acc[f][q + 4][1] = bg.y;
                acc[f][q + 4][2] = bg.x; acc[f][q + 4][3] = bg.y;
            }
        }

        const uint32_t aA = aBase + (uint32_t)((g & 1) * ABYTES_H);
        char* nbuf = Ah + ((g + 1) & 1) * ABYTES_H;

        // ---- k = 0 ----
        {
            uint32_t a0[4], a1[4];
            ldsm_x4(a0, aA);
            ldsm_x4(a1, aA + 16 * PITCH_B);
            const uint32_t* bv = fbv[0];
            const uint32_t* bg = fbg[0];
            mma_f16(acc[0][0], a0, bv + 0); mma_f16(acc[0][1], a0, bv + 2);
            mma_f16(acc[0][2], a0, bv + 4); mma_f16(acc[0][3], a0, bv + 6);
            mma_f16(acc[0][4], a0, bg + 0); mma_f16(acc[0][5], a0, bg + 2);
            mma_f16(acc[0][6], a0, bg + 4); mma_f16(acc[0][7], a0, bg + 6);
            mma_f16(acc[1][0], a1, bv + 0); mma_f16(acc[1][1], a1, bv + 2);
            mma_f16(acc[1][2], a1, bv + 4); mma_f16(acc[1][3], a1, bv + 6);
            mma_f16(acc[1][4], a1, bg + 0); mma_f16(acc[1][5], a1, bg + 2);
            mma_f16(acc[1][6], a1, bg + 4); mma_f16(acc[1][7], a1, bg + 6);
        }
        // ---- store phase-1 prefetch, issue phase 2 (chunks t=2,3) ----
        if (g < 3) {
            sts_half8(nbuf + arow * PITCH_B + ac * 8, pf0);
            sts_half8(nbuf + (arow + 32) * PITCH_B + ac * 8, pf1);
            pf0 = __ldg(reinterpret_cast<const float4*>(
                nsrc + (size_t)(arow + 64) * kD * kM + 0) + ac);
            pf1 = __ldg(reinterpret_cast<const float4*>(
                nsrc + (size_t)(arow + 96) * kD * kM + 0) + ac);
        }
        // ---- k = 1 ----
        {
            uint32_t a0[4], a1[4];
            ldsm_x4(a0, aA + 32);
            ldsm_x4(a1, aA + 16 * PITCH_B + 32);
            const uint32_t* bv = fbv[1];
            const uint32_t* bg = fbg[1];
            mma_f16(acc[0][0], a0, bv + 0); mma_f16(acc[0][1], a0, bv + 2);
            mma_f16(acc[0][2], a0, bv + 4); mma_f16(acc[0][3], a0, bv + 6);
            mma_f16(acc[0][4], a0, bg + 0); mma_f16(acc[0][5], a0, bg + 2);
            mma_f16(acc[0][6], a0, bg + 4); mma_f16(acc[0][7], a0, bg + 6);
            mma_f16(acc[1][0], a1, bv + 0); mma_f16(acc[1][1], a1, bv + 2);
            mma_f16(acc[1][2], a1, bv + 4); mma_f16(acc[1][3], a1, bv + 6);
            mma_f16(acc[1][4], a1, bg + 0); mma_f16(acc[1][5], a1, bg + 2);
            mma_f16(acc[1][6], a1, bg + 4); mma_f16(acc[1][7], a1, bg + 6);
        }

        // ---- GLU1 + layer-2 partials, quad reduce -> ps ----
        float4 w2q[4];
        #pragma unroll
        for (int q = 0; q < 4; q++)
            w2q[q] = *reinterpret_cast<const float4*>(&sW2[nh * 32 + q * 8 + hq]);

        #pragma unroll
        for (int f = 0; f < 2; f++) {
            #pragma unroll
            for (int rh = 0; rh < 2; rh++) {
                float p0 = 0.0f, p1 = 0.0f;
                #pragma unroll
                for (int q = 0; q < 4; q++) {
                    const float x0 = (acc[f][q][rh * 2 + 0] * rTa) *
                                     fast_sigmoid(acc[f][q + 4][rh * 2 + 0] * rTa);
                    const float x1 = (acc[f][q][rh * 2 + 1] * rTa) *
                                     fast_sigmoid(acc[f][q + 4][rh * 2 + 1] * rTa);
                    p0 = fmaf(x0, w2q[q].x, p0); p1 = fmaf(x0, w2q[q].y, p1);
                    p0 = fmaf(x1, w2q[q].z, p0); p1 = fmaf(x1, w2q[q].w, p1);
                }
                p0 += __shfl_xor_sync(0xffffffffu, p0, 1);
                p0 += __shfl_xor_sync(0xffffffffu, p0, 2);
                p1 += __shfl_xor_sync(0xffffffffu, p1, 1);
                p1 += __shfl_xor_sync(0xffffffffu, p1, 2);
                if ((lane & 3) == 0) {
                    const int row = mt * 32 + f * 16 + rh * 8 + (lane >> 2);
                    *reinterpret_cast<float2*>(&ps[row * 4 + nh * 2]) = make_float2(p0, p1);
                }
            }
        }

        // ---- store phase-2 prefetch ----
        if (g < 3) {
            sts_half8(nbuf + (arow + 64) * PITCH_B + ac * 8, pf0);
            sts_half8(nbuf + (arow + 96) * PITCH_B + ac * 8, pf1);
        }
        __syncthreads();   // ps visible + next A buffer complete
    }

    // ---- finalize last group ----
    if (tid < 128) {
        const float4 pp = *reinterpret_cast<const float4*>(&ps[tid * 4]);
        const float u0 = (pp.x + pp.z + sBi2[0]) * rTb;
        const float u1 = (pp.y + pp.w + sBi2[1]) * rTb;
        out[(size_t)(3 * 128 + tid) * kD + d] = u0 * fast_sigmoid(u1);
    }
}

// ---------------- launch ----------------
extern "C" void kernel_launch(void* const* d_in, const int* in_sizes, int n_in,
                              void* d_out, int out_size) {
    const float* state = (const float*)d_in[0];
    const float* w1a   = (const float*)d_in[1];
    const float* b1a   = (const float*)d_in[2];
    const float* Ta    = (const float*)d_in[3];
    const float* w1b   = (const float*)d_in[4];
    const float* b1b   = (const float*)d_in[5];
    const float* Tb    = (const float*)d_in[6];
    float* out = (float*)d_out;

    cudaFuncSetAttribute(nlm_mma_kernel,
                         cudaFuncAttributeMaxDynamicSharedMemorySize, SMEM_BYTES);

    transpose_kernel<<<dim3(kD / 32, kH2), 256>>>(w1a);
    nlm_mma_kernel<<<kD, 256, SMEM_BYTES>>>(state, b1a, Ta, w1b, b1b, Tb, out);
}